// round 1
// baseline (speedup 1.0000x reference)
#include <cuda_runtime.h>

#define BSZ  4
#define NDIM 512
#define MDIM 512
#define HDIM 128

// ---------------- device scratch (no allocs allowed) ----------------
// g_WT[half][h4][k] = float4 of W_concat[k][half*128 + 4*h4 .. +3]
__device__ float4 g_WT[2][32][128];
__device__ float  g_A[BSZ * NDIM * HDIM];   // first @ W1^T + b_concat
__device__ float  g_C[BSZ * MDIM * HDIM];   // second @ W2^T

__device__ __forceinline__ float fast_tanh(float x) {
    float y;
    asm("tanh.approx.f32 %0, %1;" : "=f"(y) : "f"(x));
    return y;
}

// ---------------- kernel 1: transpose W_concat halves ----------------
// W_concat is (128, 256) row-major. Build k-major float4 views per half.
__global__ void transpose_w_kernel(const float4* __restrict__ Wc4) {
    int t = blockIdx.x * blockDim.x + threadIdx.x;   // 0..8191
    int half = t >> 12;
    int i = t & 4095;
    int h4 = i & 31;
    int k  = i >> 5;
    // W_concat row stride = 256 floats = 64 float4
    g_WT[half][h4][k] = Wc4[k * 64 + half * 32 + h4];
}

// ---------------- kernel 2: projection GEMM ----------------
// Out[r][c] = sum_h X[r][h] * W_concat[c][off+h]  (+ bias[c] for half 0)
// 32 rows per block, 256 threads: warp -> 4 rows, lane -> cols {l, l+32, l+64, l+96}
__global__ __launch_bounds__(256) void proj_kernel(
    const float* __restrict__ first,
    const float* __restrict__ second,
    const float* __restrict__ bias)   // b_concat
{
    const int half = blockIdx.y;
    const float4* __restrict__ X4 = (const float4*)(half ? second : first);
    float* __restrict__ Out = half ? g_C : g_A;
    const float4* __restrict__ WT = &g_WT[half][0][0];

    const int row0 = blockIdx.x * 32;
    const int warp = threadIdx.x >> 5;
    const int lane = threadIdx.x & 31;

    float acc[4][4];
#pragma unroll
    for (int r = 0; r < 4; ++r)
#pragma unroll
        for (int g = 0; g < 4; ++g) acc[r][g] = 0.f;

#pragma unroll 4
    for (int h4 = 0; h4 < 32; ++h4) {
        float4 w4[4];
#pragma unroll
        for (int g = 0; g < 4; ++g)
            w4[g] = WT[h4 * 128 + lane + 32 * g];   // coalesced, L1-resident
#pragma unroll
        for (int r = 0; r < 4; ++r) {
            float4 x = X4[(row0 + warp * 4 + r) * 32 + h4];  // warp-broadcast
#pragma unroll
            for (int g = 0; g < 4; ++g) {
                acc[r][g] = fmaf(x.x, w4[g].x, acc[r][g]);
                acc[r][g] = fmaf(x.y, w4[g].y, acc[r][g]);
                acc[r][g] = fmaf(x.z, w4[g].z, acc[r][g]);
                acc[r][g] = fmaf(x.w, w4[g].w, acc[r][g]);
            }
        }
    }

#pragma unroll
    for (int r = 0; r < 4; ++r) {
        int row = row0 + warp * 4 + r;
#pragma unroll
        for (int g = 0; g < 4; ++g) {
            int col = lane + 32 * g;
            float v = acc[r][g];
            if (half == 0) v += bias[col];   // fold b_concat into A
            Out[row * HDIM + col] = v;
        }
    }
}

// ---------------- kernel 3: fused tanh-score ----------------
// out[b,n,m] = b_single + sum_k w[k] * tanh(A[b,n,k] + C[b,m,k])
// Block: 32x32 output tile. warp -> 4 n-rows, lane -> m column.
__global__ __launch_bounds__(256) void score_kernel(
    const float* __restrict__ Wsingle,
    const float* __restrict__ bsingle,
    float* __restrict__ out)
{
    __shared__ float4 a4[32][32];    // [n_local][k4]   (broadcast reads)
    __shared__ float4 cs4[32][33];   // [k4][m_local]   (+1 f4 pad: conflict-free)
    __shared__ float4 ws4[32];

    const int b  = blockIdx.z;
    const int n0 = blockIdx.x * 32;
    const int m0 = blockIdx.y * 32;
    const int tid  = threadIdx.x;
    const int warp = tid >> 5;
    const int lane = tid & 31;

    const float4* __restrict__ A4 = (const float4*)g_A + (size_t)(b * NDIM + n0) * 32;
    const float4* __restrict__ C4 = (const float4*)g_C + (size_t)(b * MDIM + m0) * 32;

#pragma unroll
    for (int t = 0; t < 4; ++t) {
        int idx = tid + t * 256;
        int i  = idx >> 5;     // row within tile
        int k4 = idx & 31;     // float4 index along H
        a4[i][k4]  = A4[i * 32 + k4];   // coalesced gmem, linear smem
        cs4[k4][i] = C4[i * 32 + k4];   // coalesced gmem; smem stride 33 -> no conflicts
    }
    if (tid < 32) ws4[tid] = ((const float4*)Wsingle)[tid];
    __syncthreads();

    float acc0 = 0.f, acc1 = 0.f, acc2 = 0.f, acc3 = 0.f;

#pragma unroll 4
    for (int k4 = 0; k4 < 32; ++k4) {
        const float4 cv = cs4[k4][lane];   // lanes consecutive -> conflict-free
        const float4 wv = ws4[k4];         // uniform broadcast

        float4 av0 = a4[warp * 4 + 0][k4];
        float4 av1 = a4[warp * 4 + 1][k4];
        float4 av2 = a4[warp * 4 + 2][k4];
        float4 av3 = a4[warp * 4 + 3][k4];

        acc0 = fmaf(wv.x, fast_tanh(av0.x + cv.x), acc0);
        acc0 = fmaf(wv.y, fast_tanh(av0.y + cv.y), acc0);
        acc0 = fmaf(wv.z, fast_tanh(av0.z + cv.z), acc0);
        acc0 = fmaf(wv.w, fast_tanh(av0.w + cv.w), acc0);

        acc1 = fmaf(wv.x, fast_tanh(av1.x + cv.x), acc1);
        acc1 = fmaf(wv.y, fast_tanh(av1.y + cv.y), acc1);
        acc1 = fmaf(wv.z, fast_tanh(av1.z + cv.z), acc1);
        acc1 = fmaf(wv.w, fast_tanh(av1.w + cv.w), acc1);

        acc2 = fmaf(wv.x, fast_tanh(av2.x + cv.x), acc2);
        acc2 = fmaf(wv.y, fast_tanh(av2.y + cv.y), acc2);
        acc2 = fmaf(wv.z, fast_tanh(av2.z + cv.z), acc2);
        acc2 = fmaf(wv.w, fast_tanh(av2.w + cv.w), acc2);

        acc3 = fmaf(wv.x, fast_tanh(av3.x + cv.x), acc3);
        acc3 = fmaf(wv.y, fast_tanh(av3.y + cv.y), acc3);
        acc3 = fmaf(wv.z, fast_tanh(av3.z + cv.z), acc3);
        acc3 = fmaf(wv.w, fast_tanh(av3.w + cv.w), acc3);
    }

    const float bs = bsingle[0];
    const int nbase = n0 + warp * 4;
    float* __restrict__ op = out + ((size_t)b * NDIM + nbase) * MDIM + m0 + lane;
    op[0 * MDIM] = acc0 + bs;
    op[1 * MDIM] = acc1 + bs;
    op[2 * MDIM] = acc2 + bs;
    op[3 * MDIM] = acc3 + bs;
}

// ---------------- launch ----------------
extern "C" void kernel_launch(void* const* d_in, const int* in_sizes, int n_in,
                              void* d_out, int out_size) {
    const float* first   = (const float*)d_in[0];
    const float* second  = (const float*)d_in[1];
    const float* Wconcat = (const float*)d_in[2];
    const float* bconcat = (const float*)d_in[3];
    const float* Wsingle = (const float*)d_in[4];
    const float* bsingle = (const float*)d_in[5];
    float* out = (float*)d_out;

    transpose_w_kernel<<<32, 256>>>((const float4*)Wconcat);
    proj_kernel<<<dim3(2048 / 32, 2), 256>>>(first, second, bconcat);
    score_kernel<<<dim3(NDIM / 32, MDIM / 32, BSZ), 256>>>(Wsingle, bsingle, out);
}

// round 4
// speedup vs baseline: 1.1276x; 1.1276x over previous
#include <cuda_runtime.h>
#include <cuda_fp16.h>

#define BSZ  4
#define NDIM 512
#define MDIM 512
#define HDIM 128

// ---------------- device scratch (no allocs allowed) ----------------
__device__ float g_A[BSZ * NDIM * HDIM];   // first @ W1^T + b_concat
__device__ float g_C[BSZ * MDIM * HDIM];   // second @ W2^T

// ---------------- kernel 1: projection GEMM (NT, W staged in smem) ----------
// Out[r][c] = sum_h X[r][h] * W_concat[c][half*128 + h]  (+ bias[c] for half 0)
// 32 rows per block, 256 threads: warp -> 4 rows, lane -> cols {l,l+32,l+64,l+96}
// W-half staged in smem in transposed-f4 layout with pad-17 (conflict-free).
__global__ __launch_bounds__(256) void proj_kernel(
    const float* __restrict__ first,
    const float* __restrict__ second,
    const float4* __restrict__ Wc4,   // W_concat as float4, row stride 64
    const float* __restrict__ bias)   // b_concat
{
    __shared__ float4 Ws[128 * 17];   // [col][f(16)+pad] -> 34.8KB

    const int half = blockIdx.y;
    const float4* __restrict__ X4 = (const float4*)(half ? second : first);
    float* __restrict__ Out = half ? g_C : g_A;

    const int row0 = blockIdx.x * 32;
    const int tid  = threadIdx.x;
    const int warp = tid >> 5;
    const int lane = tid & 31;

    float acc[4][4];
#pragma unroll
    for (int r = 0; r < 4; ++r)
#pragma unroll
        for (int g = 0; g < 4; ++g) acc[r][g] = 0.f;

#pragma unroll
    for (int chunk = 0; chunk < 2; ++chunk) {
        if (chunk) __syncthreads();
        // stage 128 cols x 16 float4 (64 h-values) — coalesced 256B runs
#pragma unroll
        for (int it = 0; it < 8; ++it) {
            int idx = tid + it * 256;          // 0..2047
            int col = idx >> 4;
            int f   = idx & 15;
            Ws[col * 17 + f] = Wc4[col * 64 + half * 32 + chunk * 16 + f];
        }
        __syncthreads();

#pragma unroll
        for (int f = 0; f < 16; ++f) {
            float4 w4[4];
#pragma unroll
            for (int g = 0; g < 4; ++g)
                w4[g] = Ws[(lane + 32 * g) * 17 + f];   // stride 68 words ≡ 4 mod 32: conflict-free
#pragma unroll
            for (int r = 0; r < 4; ++r) {
                float4 x = X4[(row0 + warp * 4 + r) * 32 + chunk * 16 + f]; // warp-broadcast
#pragma unroll
                for (int g = 0; g < 4; ++g) {
                    acc[r][g] = fmaf(x.x, w4[g].x, acc[r][g]);
                    acc[r][g] = fmaf(x.y, w4[g].y, acc[r][g]);
                    acc[r][g] = fmaf(x.z, w4[g].z, acc[r][g]);
                    acc[r][g] = fmaf(x.w, w4[g].w, acc[r][g]);
                }
            }
        }
    }

#pragma unroll
    for (int r = 0; r < 4; ++r) {
        int row = row0 + warp * 4 + r;
#pragma unroll
        for (int g = 0; g < 4; ++g) {
            int col = lane + 32 * g;
            float v = acc[r][g];
            if (half == 0) v += bias[col];   // fold b_concat into A
            Out[row * HDIM + col] = v;
        }
    }
}

// ---------------- f16x2 tanh: 2 tanh per MUFU op ----------------
__device__ __forceinline__ float2 tanh2(float a, float b) {
    __half2 h = __floats2half2_rn(a, b);            // F2FP (alu pipe)
    unsigned u = *reinterpret_cast<unsigned*>(&h);
    asm("tanh.approx.f16x2 %0, %0;" : "+r"(u));     // 1 MUFU for 2 tanh
    h = *reinterpret_cast<__half2*>(&u);
    return __half22float2(h);                       // 2x F2F
}

// ---------------- kernel 2: fused tanh-score ----------------
// out[b,n,m] = b_single + sum_k w[k] * tanh(A[b,n,k] + C[b,m,k])
__global__ __launch_bounds__(256) void score_kernel(
    const float* __restrict__ Wsingle,
    const float* __restrict__ bsingle,
    float* __restrict__ out)
{
    __shared__ float4 a4[32][32];    // [n_local][k4]   (broadcast reads)
    __shared__ float4 cs4[32][33];   // [k4][m_local]   (+1 f4 pad: conflict-free)
    __shared__ float4 ws4[32];

    const int b  = blockIdx.z;
    const int n0 = blockIdx.x * 32;
    const int m0 = blockIdx.y * 32;
    const int tid  = threadIdx.x;
    const int warp = tid >> 5;
    const int lane = tid & 31;

    const float4* __restrict__ A4 = (const float4*)g_A + (size_t)(b * NDIM + n0) * 32;
    const float4* __restrict__ C4 = (const float4*)g_C + (size_t)(b * MDIM + m0) * 32;

#pragma unroll
    for (int t = 0; t < 4; ++t) {
        int idx = tid + t * 256;
        int i  = idx >> 5;
        int k4 = idx & 31;
        a4[i][k4]  = A4[i * 32 + k4];
        cs4[k4][i] = C4[i * 32 + k4];
    }
    if (tid < 32) ws4[tid] = ((const float4*)Wsingle)[tid];
    __syncthreads();

    float acc0 = 0.f, acc1 = 0.f, acc2 = 0.f, acc3 = 0.f;

#pragma unroll 4
    for (int k4 = 0; k4 < 32; ++k4) {
        const float4 cv = cs4[k4][lane];
        const float4 wv = ws4[k4];

        float4 av0 = a4[warp * 4 + 0][k4];
        float4 av1 = a4[warp * 4 + 1][k4];
        float4 av2 = a4[warp * 4 + 2][k4];
        float4 av3 = a4[warp * 4 + 3][k4];

        float2 t;
        t = tanh2(av0.x + cv.x, av0.y + cv.y);
        acc0 = fmaf(wv.x, t.x, acc0); acc0 = fmaf(wv.y, t.y, acc0);
        t = tanh2(av0.z + cv.z, av0.w + cv.w);
        acc0 = fmaf(wv.z, t.x, acc0); acc0 = fmaf(wv.w, t.y, acc0);

        t = tanh2(av1.x + cv.x, av1.y + cv.y);
        acc1 = fmaf(wv.x, t.x, acc1); acc1 = fmaf(wv.y, t.y, acc1);
        t = tanh2(av1.z + cv.z, av1.w + cv.w);
        acc1 = fmaf(wv.z, t.x, acc1); acc1 = fmaf(wv.w, t.y, acc1);

        t = tanh2(av2.x + cv.x, av2.y + cv.y);
        acc2 = fmaf(wv.x, t.x, acc2); acc2 = fmaf(wv.y, t.y, acc2);
        t = tanh2(av2.z + cv.z, av2.w + cv.w);
        acc2 = fmaf(wv.z, t.x, acc2); acc2 = fmaf(wv.w, t.y, acc2);

        t = tanh2(av3.x + cv.x, av3.y + cv.y);
        acc3 = fmaf(wv.x, t.x, acc3); acc3 = fmaf(wv.y, t.y, acc3);
        t = tanh2(av3.z + cv.z, av3.w + cv.w);
        acc3 = fmaf(wv.z, t.x, acc3); acc3 = fmaf(wv.w, t.y, acc3);
    }

    const float bs = bsingle[0];
    const int nbase = n0 + warp * 4;
    float* __restrict__ op = out + ((size_t)b * NDIM + nbase) * MDIM + m0 + lane;
    op[0 * MDIM] = acc0 + bs;
    op[1 * MDIM] = acc1 + bs;
    op[2 * MDIM] = acc2 + bs;
    op[3 * MDIM] = acc3 + bs;
}

// ---------------- launch ----------------
extern "C" void kernel_launch(void* const* d_in, const int* in_sizes, int n_in,
                              void* d_out, int out_size) {
    const float* first   = (const float*)d_in[0];
    const float* second  = (const float*)d_in[1];
    const float* Wconcat = (const float*)d_in[2];
    const float* bconcat = (const float*)d_in[3];
    const float* Wsingle = (const float*)d_in[4];
    const float* bsingle = (const float*)d_in[5];
    float* out = (float*)d_out;

    proj_kernel<<<dim3(2048 / 32, 2), 256>>>(first, second, (const float4*)Wconcat, bconcat);
    score_kernel<<<dim3(NDIM / 32, MDIM / 32, BSZ), 256>>>(Wsingle, bsingle, out);
}

// round 5
// speedup vs baseline: 1.1412x; 1.0121x over previous
#include <cuda_runtime.h>
#include <cuda_fp16.h>

#define BSZ  4
#define NDIM 512
#define MDIM 512
#define HDIM 128
#define K2   (HDIM / 2)   // 64 half2 per row

// ---------------- device scratch (no allocs allowed) ----------------
__device__ __half2 gh_A[BSZ * NDIM * K2];   // first @ W1^T + b_concat, f16 pairs
__device__ __half2 gh_C[BSZ * MDIM * K2];   // second @ W2^T, f16 pairs

// ---------------- kernel 1: projection GEMM -> half2 output ----------------
// Thread (warp w, lane l) computes rows row0+4w..+3, cols {2l, 2l+1, 2l+64, 2l+65},
// packs (2l,2l+1) and (2l+64,2l+65) into half2 -> coalesced half2 stores.
// W staged in even/odd-column smem arrays, stride 17 uint4 (phase-conflict-free).
__global__ __launch_bounds__(256) void proj_kernel(
    const float* __restrict__ first,
    const float* __restrict__ second,
    const float4* __restrict__ Wc4,   // W_concat as float4, row stride 64
    const float* __restrict__ bias)   // b_concat
{
    __shared__ float4 WsE[64 * 17];   // even cols: [p][f(16)+pad]
    __shared__ float4 WsO[64 * 17];   // odd  cols

    const int half = blockIdx.y;
    const float4* __restrict__ X4 = (const float4*)(half ? second : first);
    __half2* __restrict__ Out = half ? gh_C : gh_A;

    const int row0 = blockIdx.x * 32;
    const int tid  = threadIdx.x;
    const int warp = tid >> 5;
    const int lane = tid & 31;

    float acc[4][4];
#pragma unroll
    for (int r = 0; r < 4; ++r)
#pragma unroll
        for (int g = 0; g < 4; ++g) acc[r][g] = 0.f;

#pragma unroll
    for (int chunk = 0; chunk < 2; ++chunk) {
        if (chunk) __syncthreads();
        // stage 128 cols x 16 float4 (64 h-values), split even/odd columns
#pragma unroll
        for (int it = 0; it < 8; ++it) {
            int idx = tid + it * 256;          // 0..2047
            int col = idx >> 4;
            int f   = idx & 15;
            float4 v = Wc4[col * 64 + half * 32 + chunk * 16 + f];
            if (col & 1) WsO[(col >> 1) * 17 + f] = v;
            else         WsE[(col >> 1) * 17 + f] = v;
        }
        __syncthreads();

#pragma unroll
        for (int f = 0; f < 16; ++f) {
            float4 w4[4];
            w4[0] = WsE[lane * 17 + f];          // col 2l
            w4[1] = WsO[lane * 17 + f];          // col 2l+1
            w4[2] = WsE[(lane + 32) * 17 + f];   // col 2l+64
            w4[3] = WsO[(lane + 32) * 17 + f];   // col 2l+65
#pragma unroll
            for (int r = 0; r < 4; ++r) {
                float4 x = X4[(row0 + warp * 4 + r) * 32 + chunk * 16 + f]; // warp-broadcast
#pragma unroll
                for (int g = 0; g < 4; ++g) {
                    acc[r][g] = fmaf(x.x, w4[g].x, acc[r][g]);
                    acc[r][g] = fmaf(x.y, w4[g].y, acc[r][g]);
                    acc[r][g] = fmaf(x.z, w4[g].z, acc[r][g]);
                    acc[r][g] = fmaf(x.w, w4[g].w, acc[r][g]);
                }
            }
        }
    }

    float b0 = 0.f, b1 = 0.f, b2 = 0.f, b3 = 0.f;
    if (half == 0) {                 // fold b_concat into A
        b0 = bias[2 * lane];     b1 = bias[2 * lane + 1];
        b2 = bias[2 * lane + 64]; b3 = bias[2 * lane + 65];
    }
#pragma unroll
    for (int r = 0; r < 4; ++r) {
        int row = row0 + warp * 4 + r;
        Out[row * K2 + lane]      = __floats2half2_rn(acc[r][0] + b0, acc[r][1] + b1);
        Out[row * K2 + 32 + lane] = __floats2half2_rn(acc[r][2] + b2, acc[r][3] + b3);
    }
}

// ---------------- kernel 2: fused tanh-score (h2 pipeline, f32 accumulate) ----
// out[b,n,m] = b_single + sum_k w[k] * tanh(A[b,n,k] + C[b,m,k])
// Per k4 (4 k = 2 half2): HADD2 -> tanh.f16x2 -> 2xF2F -> 2xFFMA  (3 issues/elem)
__global__ __launch_bounds__(256, 5) void score_kernel(
    const float* __restrict__ Wsingle,
    const float* __restrict__ bsingle,
    float* __restrict__ out)
{
    __shared__ uint2  a2s[32][32];    // [n_local][k4]  8B chunks (broadcast reads)
    __shared__ uint2  cs2[32][33];    // [k4][m_local]  +1 pad: conflict-free
    __shared__ float4 ws4[32];        // w[4k4..4k4+3]

    const int b  = blockIdx.z;
    const int n0 = blockIdx.x * 32;
    const int m0 = blockIdx.y * 32;
    const int tid  = threadIdx.x;
    const int warp = tid >> 5;
    const int lane = tid & 31;

    const uint4* __restrict__ A4 = (const uint4*)(gh_A + (size_t)(b * NDIM + n0) * K2);
    const uint4* __restrict__ C4 = (const uint4*)(gh_C + (size_t)(b * MDIM + m0) * K2);

    // stage: 32 rows x 16 uint4 per tile (coalesced 256B runs)
#pragma unroll
    for (int t = 0; t < 2; ++t) {
        int idx = tid + t * 256;      // 0..511
        int i  = idx >> 4;            // row within tile
        int f4 = idx & 15;            // uint4 chunk = k4 pair {2f4, 2f4+1}
        uint4 av = A4[i * 16 + f4];
        ((uint4*)&a2s[i][2 * f4])[0] = av;
        uint4 cv = C4[i * 16 + f4];
        cs2[2 * f4][i]     = make_uint2(cv.x, cv.y);
        cs2[2 * f4 + 1][i] = make_uint2(cv.z, cv.w);
    }
    if (tid < 32) ws4[tid] = ((const float4*)Wsingle)[tid];
    __syncthreads();

    // 8 independent f32 accumulators: [row][even/odd k]
    float accX0 = 0.f, accY0 = 0.f, accX1 = 0.f, accY1 = 0.f;
    float accX2 = 0.f, accY2 = 0.f, accX3 = 0.f, accY3 = 0.f;

#pragma unroll 4
    for (int k4 = 0; k4 < 32; ++k4) {
        const uint2  cu = cs2[k4][lane];
        const float4 wv = ws4[k4];
        const __half2 c0 = *(const __half2*)&cu.x;
        const __half2 c1 = *(const __half2*)&cu.y;

#define ROW_STEP(R, AX, AY)                                                   \
        {                                                                     \
            uint2 au = a2s[warp * 4 + R][k4];                                 \
            __half2 s0 = __hadd2(*(__half2*)&au.x, c0);                       \
            __half2 s1 = __hadd2(*(__half2*)&au.y, c1);                       \
            unsigned u0 = *(unsigned*)&s0, u1 = *(unsigned*)&s1;              \
            asm("tanh.approx.f16x2 %0, %0;" : "+r"(u0));                      \
            asm("tanh.approx.f16x2 %0, %0;" : "+r"(u1));                      \
            float2 f0 = __half22float2(*(__half2*)&u0);                       \
            float2 f1 = __half22float2(*(__half2*)&u1);                       \
            AX = fmaf(wv.x, f0.x, AX);  AY = fmaf(wv.y, f0.y, AY);            \
            AX = fmaf(wv.z, f1.x, AX);  AY = fmaf(wv.w, f1.y, AY);            \
        }
        ROW_STEP(0, accX0, accY0)
        ROW_STEP(1, accX1, accY1)
        ROW_STEP(2, accX2, accY2)
        ROW_STEP(3, accX3, accY3)
#undef ROW_STEP
    }

    const float bs = bsingle[0];
    const int nbase = n0 + warp * 4;
    float* __restrict__ op = out + ((size_t)b * NDIM + nbase) * MDIM + m0 + lane;
    op[0 * MDIM] = accX0 + accY0 + bs;
    op[1 * MDIM] = accX1 + accY1 + bs;
    op[2 * MDIM] = accX2 + accY2 + bs;
    op[3 * MDIM] = accX3 + accY3 + bs;
}

// ---------------- launch ----------------
extern "C" void kernel_launch(void* const* d_in, const int* in_sizes, int n_in,
                              void* d_out, int out_size) {
    const float* first   = (const float*)d_in[0];
    const float* second  = (const float*)d_in[1];
    const float* Wconcat = (const float*)d_in[2];
    const float* bconcat = (const float*)d_in[3];
    const float* Wsingle = (const float*)d_in[4];
    const float* bsingle = (const float*)d_in[5];
    float* out = (float*)d_out;

    proj_kernel<<<dim3(2048 / 32, 2), 256>>>(first, second, (const float4*)Wconcat, bconcat);
    score_kernel<<<dim3(NDIM / 32, MDIM / 32, BSZ), 256>>>(Wsingle, bsingle, out);
}

// round 6
// speedup vs baseline: 1.1652x; 1.0210x over previous
#include <cuda_runtime.h>
#include <cuda_fp16.h>

#define BSZ  4
#define NDIM 512
#define MDIM 512
#define HDIM 128
#define K2   (HDIM / 2)   // 64 half2 per row

// ---------------- device scratch (no allocs allowed) ----------------
__device__ __half2 gh_A[BSZ * NDIM * K2];   // first @ W1^T + b_concat, f16 pairs
__device__ __half2 gh_C[BSZ * MDIM * K2];   // second @ W2^T, f16 pairs

// ---------------- kernel 1: projection GEMM -> half2 output ----------------
// Thread (warp w, lane l) computes rows row0+4w..+3, cols {2l, 2l+1, 2l+64, 2l+65},
// packs adjacent cols into half2 -> coalesced half2 stores.
__global__ __launch_bounds__(256) void proj_kernel(
    const float* __restrict__ first,
    const float* __restrict__ second,
    const float4* __restrict__ Wc4,   // W_concat as float4, row stride 64
    const float* __restrict__ bias)   // b_concat
{
    __shared__ float4 WsE[64 * 17];   // even cols: [p][f(16)+pad]
    __shared__ float4 WsO[64 * 17];   // odd  cols

    const int half = blockIdx.y;
    const float4* __restrict__ X4 = (const float4*)(half ? second : first);
    __half2* __restrict__ Out = half ? gh_C : gh_A;

    const int row0 = blockIdx.x * 32;
    const int tid  = threadIdx.x;
    const int warp = tid >> 5;
    const int lane = tid & 31;

    float acc[4][4];
#pragma unroll
    for (int r = 0; r < 4; ++r)
#pragma unroll
        for (int g = 0; g < 4; ++g) acc[r][g] = 0.f;

#pragma unroll
    for (int chunk = 0; chunk < 2; ++chunk) {
        if (chunk) __syncthreads();
#pragma unroll
        for (int it = 0; it < 8; ++it) {
            int idx = tid + it * 256;          // 0..2047
            int col = idx >> 4;
            int f   = idx & 15;
            float4 v = Wc4[col * 64 + half * 32 + chunk * 16 + f];
            if (col & 1) WsO[(col >> 1) * 17 + f] = v;
            else         WsE[(col >> 1) * 17 + f] = v;
        }
        __syncthreads();

#pragma unroll
        for (int f = 0; f < 16; ++f) {
            float4 w4[4];
            w4[0] = WsE[lane * 17 + f];          // col 2l
            w4[1] = WsO[lane * 17 + f];          // col 2l+1
            w4[2] = WsE[(lane + 32) * 17 + f];   // col 2l+64
            w4[3] = WsO[(lane + 32) * 17 + f];   // col 2l+65
#pragma unroll
            for (int r = 0; r < 4; ++r) {
                float4 x = X4[(row0 + warp * 4 + r) * 32 + chunk * 16 + f];
#pragma unroll
                for (int g = 0; g < 4; ++g) {
                    acc[r][g] = fmaf(x.x, w4[g].x, acc[r][g]);
                    acc[r][g] = fmaf(x.y, w4[g].y, acc[r][g]);
                    acc[r][g] = fmaf(x.z, w4[g].z, acc[r][g]);
                    acc[r][g] = fmaf(x.w, w4[g].w, acc[r][g]);
                }
            }
        }
    }

    float b0 = 0.f, b1 = 0.f, b2 = 0.f, b3 = 0.f;
    if (half == 0) {                 // fold b_concat into A
        b0 = bias[2 * lane];      b1 = bias[2 * lane + 1];
        b2 = bias[2 * lane + 64]; b3 = bias[2 * lane + 65];
    }
#pragma unroll
    for (int r = 0; r < 4; ++r) {
        int row = row0 + warp * 4 + r;
        Out[row * K2 + lane]      = __floats2half2_rn(acc[r][0] + b0, acc[r][1] + b1);
        Out[row * K2 + 32 + lane] = __floats2half2_rn(acc[r][2] + b2, acc[r][3] + b3);
    }
}

// ---------------- kernel 2: fused tanh-score ----------------
// out[b,n,m] = b_single + sum_k w[k] * tanh(A[b,n,k] + C[b,m,k])
// Inner: HADD2 -> tanh.f16x2 -> HMUL2/HFMA2 (w in f16) -> 2-level f16 tree
// over 8 k -> single F2F pair + f32 FADD.  XU ops: 4 MUFU + 2 F2F per 8k-row.
__global__ __launch_bounds__(256, 5) void score_kernel(
    const float* __restrict__ Wsingle,
    const float* __restrict__ bsingle,
    float* __restrict__ out)
{
    __shared__ uint4 a4s[32][16];            // [n_local][k2]  16B chunks (broadcast)
    __shared__ uint4 cs[16][33];             // [k2][m_local]  +1 pad
    __shared__ __align__(16) uint2 wh[32];   // w as half2: wh[j] = w[4j..4j+3]

    const int b  = blockIdx.z;
    const int n0 = blockIdx.x * 32;
    const int m0 = blockIdx.y * 32;
    const int tid  = threadIdx.x;
    const int warp = tid >> 5;
    const int lane = tid & 31;

    const uint4* __restrict__ A4 = (const uint4*)(gh_A + (size_t)(b * NDIM + n0) * K2);
    const uint4* __restrict__ C4 = (const uint4*)(gh_C + (size_t)(b * MDIM + m0) * K2);

    // stage A-tile and C-tile: 512 uint4 each (coalesced 16B loads)
#pragma unroll
    for (int t = 0; t < 2; ++t) {
        int idx = tid + t * 256;
        int i  = idx >> 4;
        int f4 = idx & 15;
        a4s[i][f4] = A4[i * 16 + f4];
        cs[f4][i]  = C4[i * 16 + f4];
    }
    if (tid < 32) {                 // pack W_single to half2
        float4 w4 = ((const float4*)Wsingle)[tid];
        __half2 h01 = __floats2half2_rn(w4.x, w4.y);
        __half2 h23 = __floats2half2_rn(w4.z, w4.w);
        wh[tid] = make_uint2(*(unsigned*)&h01, *(unsigned*)&h23);
    }
    __syncthreads();

    float accX0 = 0.f, accY0 = 0.f, accX1 = 0.f, accY1 = 0.f;
    float accX2 = 0.f, accY2 = 0.f, accX3 = 0.f, accY3 = 0.f;

#pragma unroll 4
    for (int k2 = 0; k2 < 16; ++k2) {
        const uint4 cu = cs[k2][lane];
        const uint4 wu = *(const uint4*)&wh[2 * k2];
        const __half2 c0 = *(const __half2*)&cu.x;
        const __half2 c1 = *(const __half2*)&cu.y;
        const __half2 c2 = *(const __half2*)&cu.z;
        const __half2 c3 = *(const __half2*)&cu.w;
        const __half2 w0 = *(const __half2*)&wu.x;
        const __half2 w1 = *(const __half2*)&wu.y;
        const __half2 w2 = *(const __half2*)&wu.z;
        const __half2 w3 = *(const __half2*)&wu.w;

#define ROW_STEP(R, AX, AY)                                                   \
        {                                                                     \
            uint4 au = a4s[warp * 4 + R][k2];                                 \
            unsigned u0, u1, u2, u3;                                          \
            {   __half2 s;                                                    \
                s = __hadd2(*(__half2*)&au.x, c0); u0 = *(unsigned*)&s;       \
                s = __hadd2(*(__half2*)&au.y, c1); u1 = *(unsigned*)&s;       \
                s = __hadd2(*(__half2*)&au.z, c2); u2 = *(unsigned*)&s;       \
                s = __hadd2(*(__half2*)&au.w, c3); u3 = *(unsigned*)&s; }     \
            asm("tanh.approx.f16x2 %0, %0;" : "+r"(u0));                      \
            asm("tanh.approx.f16x2 %0, %0;" : "+r"(u1));                      \
            asm("tanh.approx.f16x2 %0, %0;" : "+r"(u2));                      \
            asm("tanh.approx.f16x2 %0, %0;" : "+r"(u3));                      \
            __half2 p0 = __hmul2(*(__half2*)&u0, w0);                         \
            __half2 q0 = __hfma2(*(__half2*)&u1, w1, p0);                     \
            __half2 p2 = __hmul2(*(__half2*)&u2, w2);                         \
            __half2 q1 = __hfma2(*(__half2*)&u3, w3, p2);                     \
            __half2 g  = __hadd2(q0, q1);                                     \
            AX += __low2float(g);                                             \
            AY += __high2float(g);                                            \
        }
        ROW_STEP(0, accX0, accY0)
        ROW_STEP(1, accX1, accY1)
        ROW_STEP(2, accX2, accY2)
        ROW_STEP(3, accX3, accY3)
#undef ROW_STEP
    }

    const float bs = bsingle[0];
    const int nbase = n0 + warp * 4;
    float* __restrict__ op = out + ((size_t)b * NDIM + nbase) * MDIM + m0 + lane;
    op[0 * MDIM] = accX0 + accY0 + bs;
    op[1 * MDIM] = accX1 + accY1 + bs;
    op[2 * MDIM] = accX2 + accY2 + bs;
    op[3 * MDIM] = accX3 + accY3 + bs;
}

// ---------------- launch ----------------
extern "C" void kernel_launch(void* const* d_in, const int* in_sizes, int n_in,
                              void* d_out, int out_size) {
    const float* first   = (const float*)d_in[0];
    const float* second  = (const float*)d_in[1];
    const float* Wconcat = (const float*)d_in[2];
    const float* bconcat = (const float*)d_in[3];
    const float* Wsingle = (const float*)d_in[4];
    const float* bsingle = (const float*)d_in[5];
    float* out = (float*)d_out;

    proj_kernel<<<dim3(2048 / 32, 2), 256>>>(first, second, (const float4*)Wconcat, bconcat);
    score_kernel<<<dim3(NDIM / 32, MDIM / 32, BSZ), 256>>>(Wsingle, bsingle, out);
}

// round 7
// speedup vs baseline: 1.3245x; 1.1367x over previous
#include <cuda_runtime.h>
#include <cuda_fp16.h>

#define BSZ  4
#define NDIM 512
#define MDIM 512
#define HDIM 128
#define K2   (HDIM / 2)   // 64 half2 per row

// ---------------- device scratch (no allocs allowed) ----------------
// Half2 slot h (k = 2h,2h+1): j = h>>2 (k-octet), s = h&3.
// Slot routing: j even -> slot 3 holds tanh'd values; j odd -> slots 2,3 tanh'd.
// (5/8 of values raw -> MUFU tanh in score kernel; 3/8 pre-tanh'd -> identity path)
__device__ __half2 gh_A[BSZ * NDIM * K2];
__device__ __half2 gh_C[BSZ * MDIM * K2];

__device__ __forceinline__ float ftanh(float x) {
    float y;
    asm("tanh.approx.f32 %0, %1;" : "=f"(y) : "f"(x));
    return y;
}

// ---------------- kernel 1: projection GEMM -> routed half2 output ----------
__global__ __launch_bounds__(256) void proj_kernel(
    const float* __restrict__ first,
    const float* __restrict__ second,
    const float4* __restrict__ Wc4,   // W_concat as float4, row stride 64
    const float* __restrict__ bias)   // b_concat
{
    __shared__ float4 WsE[64 * 17];   // even cols: [p][f(16)+pad]
    __shared__ float4 WsO[64 * 17];   // odd  cols

    const int half = blockIdx.y;
    const float4* __restrict__ X4 = (const float4*)(half ? second : first);
    __half2* __restrict__ Out = half ? gh_C : gh_A;

    const int row0 = blockIdx.x * 32;
    const int tid  = threadIdx.x;
    const int warp = tid >> 5;
    const int lane = tid & 31;

    float acc[4][4];
#pragma unroll
    for (int r = 0; r < 4; ++r)
#pragma unroll
        for (int g = 0; g < 4; ++g) acc[r][g] = 0.f;

#pragma unroll
    for (int chunk = 0; chunk < 2; ++chunk) {
        if (chunk) __syncthreads();
#pragma unroll
        for (int it = 0; it < 8; ++it) {
            int idx = tid + it * 256;          // 0..2047
            int col = idx >> 4;
            int f   = idx & 15;
            float4 v = Wc4[col * 64 + half * 32 + chunk * 16 + f];
            if (col & 1) WsO[(col >> 1) * 17 + f] = v;
            else         WsE[(col >> 1) * 17 + f] = v;
        }
        __syncthreads();

#pragma unroll
        for (int f = 0; f < 16; ++f) {
            float4 w4[4];
            w4[0] = WsE[lane * 17 + f];          // col 2l
            w4[1] = WsO[lane * 17 + f];          // col 2l+1
            w4[2] = WsE[(lane + 32) * 17 + f];   // col 2l+64
            w4[3] = WsO[(lane + 32) * 17 + f];   // col 2l+65
#pragma unroll
            for (int r = 0; r < 4; ++r) {
                float4 x = X4[(row0 + warp * 4 + r) * 32 + chunk * 16 + f];
#pragma unroll
                for (int g = 0; g < 4; ++g) {
                    acc[r][g] = fmaf(x.x, w4[g].x, acc[r][g]);
                    acc[r][g] = fmaf(x.y, w4[g].y, acc[r][g]);
                    acc[r][g] = fmaf(x.z, w4[g].z, acc[r][g]);
                    acc[r][g] = fmaf(x.w, w4[g].w, acc[r][g]);
                }
            }
        }
    }

    float b0 = 0.f, b1 = 0.f, b2 = 0.f, b3 = 0.f;
    if (half == 0) {                 // fold b_concat into A
        b0 = bias[2 * lane];      b1 = bias[2 * lane + 1];
        b2 = bias[2 * lane + 64]; b3 = bias[2 * lane + 65];
    }

    // slot routing flag: h1 = lane, h2 = lane+32 -> same (j parity, s)
    const int j = lane >> 2, s = lane & 3;
    const bool tflag = (j & 1) ? (s >= 2) : (s == 3);
    const float CL = 0.9990234375f;  // 1 - 2^-10  (keeps d >= 0.00195)

#pragma unroll
    for (int r = 0; r < 4; ++r) {
        int row = row0 + warp * 4 + r;
        float v0 = acc[r][0] + b0, v1 = acc[r][1] + b1;
        float v2 = acc[r][2] + b2, v3 = acc[r][3] + b3;
        if (tflag) {
            v0 = fminf(fmaxf(ftanh(v0), -CL), CL);
            v1 = fminf(fmaxf(ftanh(v1), -CL), CL);
            v2 = fminf(fmaxf(ftanh(v2), -CL), CL);
            v3 = fminf(fmaxf(ftanh(v3), -CL), CL);
        }
        Out[row * K2 + lane]      = __floats2half2_rn(v0, v1);
        Out[row * K2 + 32 + lane] = __floats2half2_rn(v2, v3);
    }
}

// ---------------- identity-path tanh: (ta+tc)/(1+ta*tc), MUFU-free ----------
// bit-trick rcp guess + 2 Newton steps, all f16x2 on FMA/ALU pipes.
__device__ __forceinline__ __half2 ident2(__half2 ta, __half2 tc) {
    const unsigned oneu = 0x3C003C00u;
    const __half2 one = *(const __half2*)&oneu;
    __half2 d = __hfma2(ta, tc, one);          // 1 + ta*tc  (>= 0.00195)
    __half2 N = __hadd2(ta, tc);
    unsigned du = *(unsigned*)&d;
    unsigned ndu = du ^ 0x80008000u;           // -d  (LOP3, alu)
    __half2 nd = *(__half2*)&ndu;
    unsigned r0u = 0x78007800u - du;           // rcp guess, err in (-12.5%, 0]
    __half2 R = *(__half2*)&r0u;
    __half2 e = __hfma2(nd, R, one);           // Newton 1
    R = __hfma2(R, e, R);
    e = __hfma2(nd, R, one);                   // Newton 2 (fused into product)
    __half2 t = __hmul2(N, R);
    return __hfma2(t, e, t);                   // N*R*(1+e)
}

// ---------------- kernel 2: fused tanh-score (hybrid MUFU/identity) ---------
__global__ __launch_bounds__(256, 4) void score_kernel(
    const float* __restrict__ Wsingle,
    const float* __restrict__ bsingle,
    float* __restrict__ out)
{
    __shared__ uint4 a4s[32][16];            // [n_local][k2]  (broadcast)
    __shared__ uint4 cs[16][33];             // [k2][m_local]  +1 pad
    __shared__ __align__(16) uint2 wh[32];   // w as half2

    const int b  = blockIdx.z;
    const int n0 = blockIdx.x * 32;
    const int m0 = blockIdx.y * 32;
    const int tid  = threadIdx.x;
    const int warp = tid >> 5;
    const int lane = tid & 31;

    const uint4* __restrict__ A4 = (const uint4*)(gh_A + (size_t)(b * NDIM + n0) * K2);
    const uint4* __restrict__ C4 = (const uint4*)(gh_C + (size_t)(b * MDIM + m0) * K2);

#pragma unroll
    for (int t = 0; t < 2; ++t) {
        int idx = tid + t * 256;
        int i  = idx >> 4;
        int f4 = idx & 15;
        a4s[i][f4] = A4[i * 16 + f4];
        cs[f4][i]  = C4[i * 16 + f4];
    }
    if (tid < 32) {
        float4 w4 = ((const float4*)Wsingle)[tid];
        __half2 h01 = __floats2half2_rn(w4.x, w4.y);
        __half2 h23 = __floats2half2_rn(w4.z, w4.w);
        wh[tid] = make_uint2(*(unsigned*)&h01, *(unsigned*)&h23);
    }
    __syncthreads();

    float accX0 = 0.f, accY0 = 0.f, accX1 = 0.f, accY1 = 0.f;
    float accX2 = 0.f, accY2 = 0.f, accX3 = 0.f, accY3 = 0.f;

#define H2(u) (*(__half2*)&(u))
#define MUFU_T(au_, cu_, out_)                                                \
    {   __half2 s_ = __hadd2(H2(au_), H2(cu_));                               \
        unsigned su_ = *(unsigned*)&s_;                                       \
        asm("tanh.approx.f16x2 %0, %0;" : "+r"(su_));                         \
        out_ = *(__half2*)&su_; }

#define ROW_STEP(K2I, ODD, AX, AY)                                            \
    {   uint4 au = a4s[warp * 4 + R_][K2I];                                   \
        __half2 t0, t1, t2, t3;                                               \
        MUFU_T(au.x, cu.x, t0)                                                \
        MUFU_T(au.y, cu.y, t1)                                                \
        if (ODD) { t2 = ident2(H2(au.z), H2(cu.z)); }                         \
        else     { MUFU_T(au.z, cu.z, t2) }                                   \
        t3 = ident2(H2(au.w), H2(cu.w));                                      \
        __half2 p0 = __hmul2(t0, w0);                                         \
        __half2 q0 = __hfma2(t1, w1, p0);                                     \
        __half2 p2 = __hmul2(t2, w2);                                         \
        __half2 q1 = __hfma2(t3, w3, p2);                                     \
        __half2 g  = __hadd2(q0, q1);                                         \
        AX += __low2float(g);                                                 \
        AY += __high2float(g); }

#define K2_BODY(K2I, ODD)                                                     \
    {   const uint4 cu = cs[K2I][lane];                                       \
        const uint4 wu = *(const uint4*)&wh[2 * (K2I)];                       \
        const __half2 w0 = H2(wu.x), w1 = H2(wu.y);                           \
        const __half2 w2 = H2(wu.z), w3 = H2(wu.w);                           \
        { const int R_ = 0; ROW_STEP(K2I, ODD, accX0, accY0) }                \
        { const int R_ = 1; ROW_STEP(K2I, ODD, accX1, accY1) }                \
        { const int R_ = 2; ROW_STEP(K2I, ODD, accX2, accY2) }                \
        { const int R_ = 3; ROW_STEP(K2I, ODD, accX3, accY3) } }

#pragma unroll 2
    for (int q = 0; q < 8; ++q) {
        K2_BODY(2 * q,     false)   // even k2: 3 MUFU + 1 identity
        K2_BODY(2 * q + 1, true)    // odd  k2: 2 MUFU + 2 identity
    }
#undef K2_BODY
#undef ROW_STEP
#undef MUFU_T
#undef H2

    const float bs = bsingle[0];
    const int nbase = n0 + warp * 4;
    float* __restrict__ op = out + ((size_t)b * NDIM + nbase) * MDIM + m0 + lane;
    op[0 * MDIM] = accX0 + accY0 + bs;
    op[1 * MDIM] = accX1 + accY1 + bs;
    op[2 * MDIM] = accX2 + accY2 + bs;
    op[3 * MDIM] = accX3 + accY3 + bs;
}

// ---------------- launch ----------------
extern "C" void kernel_launch(void* const* d_in, const int* in_sizes, int n_in,
                              void* d_out, int out_size) {
    const float* first   = (const float*)d_in[0];
    const float* second  = (const float*)d_in[1];
    const float* Wconcat = (const float*)d_in[2];
    const float* bconcat = (const float*)d_in[3];
    const float* Wsingle = (const float*)d_in[4];
    const float* bsingle = (const float*)d_in[5];
    float* out = (float*)d_out;

    proj_kernel<<<dim3(2048 / 32, 2), 256>>>(first, second, (const float4*)Wconcat, bconcat);
    score_kernel<<<dim3(NDIM / 32, MDIM / 32, BSZ), 256>>>(Wsingle, bsingle, out);
}